// round 6
// baseline (speedup 1.0000x reference)
#include <cuda_runtime.h>
#include <cuda_fp16.h>

// FreqGrid triplane encoder. R6:
//  - no boundary selects: coords in [-1,1) => pt in [0,255]; wx/wy==0 exactly
//    whenever x0/y0==255, so unclamped corner reads are weight-0. Grid scratch
//    padded (zero-init) so those reads stay in-bounds and finite.
//  - __launch_bounds__(256,6) to target <=40 regs -> 48 warps/SM
//  - fp16 transposed grid (48 MB, L2-resident), swizzled transpose

#define RR 256
#define CHN 128
#define PLANE_ELEMS (RR * RR)              // 65536
#define GT_ELEMS (3 * PLANE_ELEMS * CHN)   // 48 MB of halfs
#define GT_PAD (33024)                     // covers +dy+dx overrun at last texel

__device__ __half g_grid_t[GT_ELEMS + GT_PAD];

// swizzled half-index for (spatial row s, channel ch) in a 64x128 tile
__device__ __forceinline__ int sw_idx(int s, int ch) {
    int chunk = (ch >> 3) ^ ((s >> 2) & 15);
    return s * 128 + (chunk << 3) + (ch & 7);
}

// ---------------------------------------------------------------------------
// Transpose + quantize: in[p][ch][s] -> g_grid_t[p][s][ch] (fp16)
// ---------------------------------------------------------------------------
__global__ void __launch_bounds__(256) transpose_kernel(const float* __restrict__ g) {
    __shared__ __half tile[64 * 128];
    const int p  = blockIdx.y;
    const int s0 = blockIdx.x << 6;
    const int tid = threadIdx.x;

    const float* in = g + (size_t)p * CHN * PLANE_ELEMS + s0;

    #pragma unroll
    for (int i = 0; i < 8; i++) {
        int u  = i * 256 + tid;
        int q  = u & 15;     // float4 index within 64 spatial
        int ch = u >> 4;     // 0..127
        float4 f = *(const float4*)(in + (size_t)ch * PLANE_ELEMS + 4 * q);
        tile[sw_idx(4 * q + 0, ch)] = __float2half_rn(f.x);
        tile[sw_idx(4 * q + 1, ch)] = __float2half_rn(f.y);
        tile[sw_idx(4 * q + 2, ch)] = __float2half_rn(f.z);
        tile[sw_idx(4 * q + 3, ch)] = __float2half_rn(f.w);
    }
    __syncthreads();

    __half* outp = g_grid_t + (size_t)p * PLANE_ELEMS * CHN + (size_t)s0 * CHN;
    #pragma unroll
    for (int i = 0; i < 4; i++) {
        int u  = i * 256 + tid;
        int c8 = u & 15;     // channel octet 0..15
        int s  = u >> 4;     // 0..63
        int chunk = c8 ^ ((s >> 2) & 15);
        uint4 val = *(const uint4*)&tile[s * 128 + (chunk << 3)];
        *(uint4*)(outp + s * CHN + 8 * c8) = val;
    }
}

// ---------------------------------------------------------------------------
// Gather + basis: half-warp per point, lane owns output channel c = lane&15
// ---------------------------------------------------------------------------
__device__ __forceinline__ void load_corners(const uint4* __restrict__ gb,
                                             int off, uint4* v) {
    v[0] = __ldg(&gb[off]);
    v[1] = __ldg(&gb[off + 16]);       // +x texel
    v[2] = __ldg(&gb[off + 4096]);     // +y row
    v[3] = __ldg(&gb[off + 4112]);
}

__device__ __forceinline__ void blend_plane(const uint4* v, float wxd, float wyd,
                                            float kdd, const float* frh,
                                            float& acc0, float& acc1) {
    __half2 w00 = __float2half2_rn((1.0f - wxd) * (1.0f - wyd));
    __half2 w01 = __float2half2_rn(wxd * (1.0f - wyd));
    __half2 w10 = __float2half2_rn((1.0f - wxd) * wyd);
    __half2 w11 = __float2half2_rn(wxd * wyd);

    const __half2* c0 = (const __half2*)&v[0];
    const __half2* c1 = (const __half2*)&v[1];
    const __half2* c2 = (const __half2*)&v[2];
    const __half2* c3 = (const __half2*)&v[3];

    #pragma unroll
    for (int q = 0; q < 4; q++) {
        __half2 cf = __hmul2(w00, c0[q]);
        cf = __hfma2(w01, c1[q], cf);
        cf = __hfma2(w10, c2[q], cf);
        cf = __hfma2(w11, c3[q], cf);
        float2 f = __half22float2(cf);
        acc0 = fmaf(f.x, __cosf(kdd * frh[2 * q]),     acc0);
        acc1 = fmaf(f.y, __cosf(kdd * frh[2 * q + 1]), acc1);
    }
}

template <int PAIRS>
__global__ void __launch_bounds__(256, 6)
freqgrid_kernel(const float* __restrict__ coords,
                const float* __restrict__ freqs,
                float* __restrict__ out, int N) {
    const int warp = (blockIdx.x * blockDim.x + threadIdx.x) >> 5;
    const int lane = threadIdx.x & 31;
    const int sub  = lane >> 4;     // 0: point A, 1: point B
    const int cl   = lane & 15;     // output channel / uint4 slot

    // Per-lane frequency constants for channels 8*cl + j
    float frh[8];
    #pragma unroll
    for (int j = 0; j < 8; j++) {
        float fq = freqs[8 * cl + j];
        fq = fminf(fmaxf(fq, 0.0f), 1.0f);
        frh[j] = exp2f(fq * 8.0f) - 0.5f;
    }

    const float PI_OVER_R = 3.14159265358979323846f / 256.0f;
    const float KC = PI_OVER_R * 0.5f;
    const uint4* __restrict__ gb = (const uint4*)g_grid_t;   // texel = 16 uint4

    const int base0 = warp * (2 * PAIRS);
    #pragma unroll
    for (int t = 0; t < PAIRS; t++) {
        const int nb = base0 + 2 * t;
        if (nb >= N) return;
        const int n = min(nb + sub, N - 1);

        float pt0 = fmaf(coords[3 * n + 0], 127.5f, 127.5f);
        float pt1 = fmaf(coords[3 * n + 1], 127.5f, 127.5f);
        float pt2 = fmaf(coords[3 * n + 2], 127.5f, 127.5f);

        float kd0 = fmaf(pt0, PI_OVER_R, KC);
        float kd1 = fmaf(pt1, PI_OVER_R, KC);
        float kd2 = fmaf(pt2, PI_OVER_R, KC);

        // plane d samples (ix,iy) from pt[{1,0,0}], pt[{2,2,1}]
        int x0a = (int)pt1, y0a = (int)pt2;        // plane 0
        int x0b = (int)pt0, y0b = (int)pt2;        // plane 1
        int x0c = (int)pt0, y0c = (int)pt1;        // plane 2

        float wxa = pt1 - (float)x0a, wya = pt2 - (float)y0a;
        float wxb = pt0 - (float)x0b, wyb = pt2 - (float)y0b;
        float wxc = pt0 - (float)x0c, wyc = pt1 - (float)y0c;

        int offa = ((y0a << 8) + x0a) * 16 + cl;
        int offb = ((PLANE_ELEMS + (y0b << 8) + x0b) * 16) + cl;
        int offc = ((2 * PLANE_ELEMS + (y0c << 8) + x0c) * 16) + cl;

        float acc0 = 0.0f, acc1 = 0.0f;
        uint4 va[4], vb[4];

        // 2-deep software pipeline over the 3 planes
        load_corners(gb, offa, va);
        load_corners(gb, offb, vb);
        blend_plane(va, wxa, wya, kd0, frh, acc0, acc1);
        load_corners(gb, offc, va);
        blend_plane(vb, wxb, wyb, kd1, frh, acc0, acc1);
        blend_plane(va, wxc, wyc, kd2, frh, acc0, acc1);

        if (nb + sub < N) {
            out[(size_t)n * 16 + cl] = 2.0f * (acc0 + acc1);
        }
    }
}

// ---------------------------------------------------------------------------
// Harness entry
// ---------------------------------------------------------------------------
extern "C" void kernel_launch(void* const* d_in, const int* in_sizes, int n_in,
                              void* d_out, int out_size) {
    const float* coords = (const float*)d_in[0];
    const float* grid   = (const float*)d_in[1];
    const float* freqs  = (const float*)d_in[2];
    float* out = (float*)d_out;

    const int N = in_sizes[0] / 3;

    dim3 tg(PLANE_ELEMS / 64, 3);
    transpose_kernel<<<tg, 256>>>(grid);

    constexpr int PAIRS = 4;                       // 8 points per warp
    const int pts_per_warp = 2 * PAIRS;
    const int warps = (N + pts_per_warp - 1) / pts_per_warp;
    const int threads = 256;
    const int blocks = (warps * 32 + threads - 1) / threads;
    freqgrid_kernel<PAIRS><<<blocks, threads>>>(coords, freqs, out, N);
}

// round 7
// speedup vs baseline: 1.0141x; 1.0141x over previous
#include <cuda_runtime.h>
#include <cuda_fp16.h>

// FreqGrid triplane encoder. R7:
//  - padded grid + compile-time corner offsets (no boundary selects; coords in
//    [-1,1) => top-edge corners carry exactly-zero weights)
//  - plain launch_bounds(256): let regs float (~50) for full MLP batch
//  - coords for all PAIRS iterations prefetched before the main loop
//  - fp16 transposed grid (48 MB, L2-resident), swizzled transpose

#define RR 256
#define CHN 128
#define PLANE_ELEMS (RR * RR)              // 65536
#define GT_ELEMS (3 * PLANE_ELEMS * CHN)   // 48 MB of halfs
#define GT_PAD (33024)                     // covers +row+texel overrun

__device__ __half g_grid_t[GT_ELEMS + GT_PAD];

// swizzled half-index for (spatial row s, channel ch) in a 64x128 tile
__device__ __forceinline__ int sw_idx(int s, int ch) {
    int chunk = (ch >> 3) ^ ((s >> 2) & 15);
    return s * 128 + (chunk << 3) + (ch & 7);
}

// ---------------------------------------------------------------------------
// Transpose + quantize: in[p][ch][s] -> g_grid_t[p][s][ch] (fp16)
// ---------------------------------------------------------------------------
__global__ void __launch_bounds__(256) transpose_kernel(const float* __restrict__ g) {
    __shared__ __half tile[64 * 128];
    const int p  = blockIdx.y;
    const int s0 = blockIdx.x << 6;
    const int tid = threadIdx.x;

    const float* in = g + (size_t)p * CHN * PLANE_ELEMS + s0;

    #pragma unroll
    for (int i = 0; i < 8; i++) {
        int u  = i * 256 + tid;
        int q  = u & 15;     // float4 index within 64 spatial
        int ch = u >> 4;     // 0..127
        float4 f = *(const float4*)(in + (size_t)ch * PLANE_ELEMS + 4 * q);
        tile[sw_idx(4 * q + 0, ch)] = __float2half_rn(f.x);
        tile[sw_idx(4 * q + 1, ch)] = __float2half_rn(f.y);
        tile[sw_idx(4 * q + 2, ch)] = __float2half_rn(f.z);
        tile[sw_idx(4 * q + 3, ch)] = __float2half_rn(f.w);
    }
    __syncthreads();

    __half* outp = g_grid_t + (size_t)p * PLANE_ELEMS * CHN + (size_t)s0 * CHN;
    #pragma unroll
    for (int i = 0; i < 4; i++) {
        int u  = i * 256 + tid;
        int c8 = u & 15;     // channel octet 0..15
        int s  = u >> 4;     // 0..63
        int chunk = c8 ^ ((s >> 2) & 15);
        uint4 val = *(const uint4*)&tile[s * 128 + (chunk << 3)];
        *(uint4*)(outp + s * CHN + 8 * c8) = val;
    }
}

// ---------------------------------------------------------------------------
// Gather + basis: half-warp per point, lane owns output channel c = lane&15
// ---------------------------------------------------------------------------
__device__ __forceinline__ void load_corners(const uint4* __restrict__ gb,
                                             int off, uint4* v) {
    v[0] = __ldg(&gb[off]);
    v[1] = __ldg(&gb[off + 16]);       // +x texel
    v[2] = __ldg(&gb[off + 4096]);     // +y row
    v[3] = __ldg(&gb[off + 4112]);
}

__device__ __forceinline__ void blend_plane(const uint4* v, float wxd, float wyd,
                                            float kdd, const float* frh,
                                            float& acc0, float& acc1) {
    __half2 w00 = __float2half2_rn((1.0f - wxd) * (1.0f - wyd));
    __half2 w01 = __float2half2_rn(wxd * (1.0f - wyd));
    __half2 w10 = __float2half2_rn((1.0f - wxd) * wyd);
    __half2 w11 = __float2half2_rn(wxd * wyd);

    const __half2* c0 = (const __half2*)&v[0];
    const __half2* c1 = (const __half2*)&v[1];
    const __half2* c2 = (const __half2*)&v[2];
    const __half2* c3 = (const __half2*)&v[3];

    #pragma unroll
    for (int q = 0; q < 4; q++) {
        __half2 cf = __hmul2(w00, c0[q]);
        cf = __hfma2(w01, c1[q], cf);
        cf = __hfma2(w10, c2[q], cf);
        cf = __hfma2(w11, c3[q], cf);
        float2 f = __half22float2(cf);
        acc0 = fmaf(f.x, __cosf(kdd * frh[2 * q]),     acc0);
        acc1 = fmaf(f.y, __cosf(kdd * frh[2 * q + 1]), acc1);
    }
}

template <int PAIRS>
__global__ void __launch_bounds__(256)
freqgrid_kernel(const float* __restrict__ coords,
                const float* __restrict__ freqs,
                float* __restrict__ out, int N) {
    const int warp = (blockIdx.x * blockDim.x + threadIdx.x) >> 5;
    const int lane = threadIdx.x & 31;
    const int sub  = lane >> 4;     // 0: point A, 1: point B
    const int cl   = lane & 15;     // output channel / uint4 slot

    // Per-lane frequency constants for channels 8*cl + j
    float frh[8];
    #pragma unroll
    for (int j = 0; j < 8; j++) {
        float fq = freqs[8 * cl + j];
        fq = fminf(fmaxf(fq, 0.0f), 1.0f);
        frh[j] = exp2f(fq * 8.0f) - 0.5f;
    }

    const float PI_OVER_R = 3.14159265358979323846f / 256.0f;
    const float KC = PI_OVER_R * 0.5f;
    const uint4* __restrict__ gb = (const uint4*)g_grid_t;   // texel = 16 uint4

    const int base0 = warp * (2 * PAIRS);

    // Prefetch this lane's coords for all iterations (breaks the per-iter
    // LDG->addr->LDG dependency chain head).
    float c0[PAIRS], c1[PAIRS], c2[PAIRS];
    #pragma unroll
    for (int t = 0; t < PAIRS; t++) {
        int n = min(base0 + 2 * t + sub, N - 1);
        c0[t] = __ldg(&coords[3 * n + 0]);
        c1[t] = __ldg(&coords[3 * n + 1]);
        c2[t] = __ldg(&coords[3 * n + 2]);
    }

    #pragma unroll
    for (int t = 0; t < PAIRS; t++) {
        const int nb = base0 + 2 * t;
        if (nb >= N) return;
        const int n = min(nb + sub, N - 1);

        float pt0 = fmaf(c0[t], 127.5f, 127.5f);
        float pt1 = fmaf(c1[t], 127.5f, 127.5f);
        float pt2 = fmaf(c2[t], 127.5f, 127.5f);

        float kd0 = fmaf(pt0, PI_OVER_R, KC);
        float kd1 = fmaf(pt1, PI_OVER_R, KC);
        float kd2 = fmaf(pt2, PI_OVER_R, KC);

        // plane d samples (ix,iy) from pt[{1,0,0}], pt[{2,2,1}]
        int x0a = (int)pt1, y0a = (int)pt2;        // plane 0
        int x0b = (int)pt0, y0b = (int)pt2;        // plane 1
        int x0c = (int)pt0, y0c = (int)pt1;        // plane 2

        float wxa = pt1 - (float)x0a, wya = pt2 - (float)y0a;
        float wxb = pt0 - (float)x0b, wyb = pt2 - (float)y0b;
        float wxc = pt0 - (float)x0c, wyc = pt1 - (float)y0c;

        int offa = ((y0a << 8) + x0a) * 16 + cl;
        int offb = ((PLANE_ELEMS + (y0b << 8) + x0b) * 16) + cl;
        int offc = ((2 * PLANE_ELEMS + (y0c << 8) + x0c) * 16) + cl;

        float acc0 = 0.0f, acc1 = 0.0f;
        uint4 va[4], vb[4];

        // 2-deep software pipeline over the 3 planes
        load_corners(gb, offa, va);
        load_corners(gb, offb, vb);
        blend_plane(va, wxa, wya, kd0, frh, acc0, acc1);
        load_corners(gb, offc, va);
        blend_plane(vb, wxb, wyb, kd1, frh, acc0, acc1);
        blend_plane(va, wxc, wyc, kd2, frh, acc0, acc1);

        if (nb + sub < N) {
            out[n * 16 + cl] = 2.0f * (acc0 + acc1);
        }
    }
}

// ---------------------------------------------------------------------------
// Harness entry
// ---------------------------------------------------------------------------
extern "C" void kernel_launch(void* const* d_in, const int* in_sizes, int n_in,
                              void* d_out, int out_size) {
    const float* coords = (const float*)d_in[0];
    const float* grid   = (const float*)d_in[1];
    const float* freqs  = (const float*)d_in[2];
    float* out = (float*)d_out;

    const int N = in_sizes[0] / 3;

    dim3 tg(PLANE_ELEMS / 64, 3);
    transpose_kernel<<<tg, 256>>>(grid);

    constexpr int PAIRS = 4;                       // 8 points per warp
    const int pts_per_warp = 2 * PAIRS;
    const int warps = (N + pts_per_warp - 1) / pts_per_warp;
    const int threads = 256;
    const int blocks = (warps * 32 + threads - 1) / threads;
    freqgrid_kernel<PAIRS><<<blocks, threads>>>(coords, freqs, out, N);
}